// round 2
// baseline (speedup 1.0000x reference)
#include <cuda_runtime.h>
#include <cuda_bf16.h>

// Box-sum 8x8 stride 4 over (8,32,512,512) fp32 NCHW -> (8,32,127,127).
// G[g][ox] = sum over input rows [4g,4g+4), cols [4ox,4ox+8).
// out[r][ox] = G[r][ox] + G[r+1][ox].
// No smem: thread t reads its 8 columns as two 16B-aligned float4 loads per
// row, directly from global. Warp-level: load "a" is a contiguous 512B
// segment, load "b" the same lines shifted 16B (L1 hit). 8 independent
// LDG.128 in flight per thread per group; no barriers.

#define IN_H 512
#define IN_W 512
#define OUT_H 127
#define OUT_W 127
#define BAND 16          // output rows per block band
#define THREADS 128

__global__ __launch_bounds__(THREADS)
void boxsum8s4_kernel(const float* __restrict__ x, float* __restrict__ y) {
    const int plane = blockIdx.x;          // 0..255  (n*32 + c)
    const int band  = blockIdx.y;          // 0..7
    const int r0 = band * BAND;
    const int r1 = min(r0 + BAND, OUT_H);  // outputs [r0, r1)

    const int tid = threadIdx.x;           // 0..127
    if (tid >= OUT_W) return;

    const float* xp = x + (size_t)plane * IN_H * IN_W + 4 * tid;
    float*       yp = y + (size_t)plane * OUT_H * OUT_W + tid;

    float prevG = 0.0f;

    // Groups g = r0 .. r1 inclusive; group g covers input rows [4g, 4g+4).
    for (int g = r0; g <= r1; ++g) {
        const float* base = xp + (size_t)(4 * g) * IN_W;

        // Issue all 8 loads up front (independent -> MLP=8).
        float4 a0 = *(const float4*)(base + 0 * IN_W);
        float4 b0 = *(const float4*)(base + 0 * IN_W + 4);
        float4 a1 = *(const float4*)(base + 1 * IN_W);
        float4 b1 = *(const float4*)(base + 1 * IN_W + 4);
        float4 a2 = *(const float4*)(base + 2 * IN_W);
        float4 b2 = *(const float4*)(base + 2 * IN_W + 4);
        float4 a3 = *(const float4*)(base + 3 * IN_W);
        float4 b3 = *(const float4*)(base + 3 * IN_W + 4);

        float G = ((a0.x + a0.y) + (a0.z + a0.w)) + ((b0.x + b0.y) + (b0.z + b0.w))
                + ((a1.x + a1.y) + (a1.z + a1.w)) + ((b1.x + b1.y) + (b1.z + b1.w))
                + ((a2.x + a2.y) + (a2.z + a2.w)) + ((b2.x + b2.y) + (b2.z + b2.w))
                + ((a3.x + a3.y) + (a3.z + a3.w)) + ((b3.x + b3.y) + (b3.z + b3.w));

        if (g > r0) {
            yp[(size_t)(g - 1) * OUT_W] = prevG + G;
        }
        prevG = G;
    }
}

extern "C" void kernel_launch(void* const* d_in, const int* in_sizes, int n_in,
                              void* d_out, int out_size) {
    const float* x = (const float*)d_in[0];
    float* y = (float*)d_out;
    dim3 grid(8 * 32, (OUT_H + BAND - 1) / BAND);   // 256 planes x 8 bands
    boxsum8s4_kernel<<<grid, THREADS>>>(x, y);
}

// round 3
// speedup vs baseline: 1.2060x; 1.2060x over previous
#include <cuda_runtime.h>
#include <cuda_bf16.h>

// Box-sum 8x8 stride 4 over (8,32,512,512) fp32 NCHW -> (8,32,127,127).
// Per 4-row group g: thread t accumulates P = sum of its own float4 column
// group (cols 4t..4t+3) over the 4 rows -> each input element loaded exactly
// once, coalesced, no overlap. G[ox] = P[ox] + P[ox+1] via __shfl_down; the
// lane-31 seam uses an extra float4 loaded by lane 0 of the next segment
// (warps 0-2 only; col 127 output doesn't exist so warp 3 needs no seam).
// out[g-1] = G_{g-1} + G_g. No smem, no barriers.

#define IN_W4 128        // 512 floats = 128 float4 per row
#define OUT_H 127
#define OUT_W 127
#define BAND 16          // output rows per block band
#define THREADS 128

__global__ __launch_bounds__(THREADS)
void boxsum8s4_kernel(const float* __restrict__ x, float* __restrict__ y) {
    const int plane = blockIdx.x;            // 0..255
    const int band  = blockIdx.y;            // 0..7
    const int r0 = band * BAND;
    const int r1 = min(r0 + BAND, OUT_H);

    const int tid  = threadIdx.x;            // 0..127 = float4 column group
    const int lane = tid & 31;
    const int warp = tid >> 5;

    const float4* xp = (const float4*)x + (size_t)plane * 512 * IN_W4 + tid;
    float*        yp = y + (size_t)plane * OUT_H * OUT_W + tid;

    const bool do_extra = (lane == 0) && (warp < 3);

    float prevG = 0.0f;

    for (int g = r0; g <= r1; ++g) {
        const float4* row = xp + (size_t)(4 * g) * IN_W4;

        float P = 0.0f, E = 0.0f;
        #pragma unroll
        for (int ry = 0; ry < 4; ++ry) {
            float4 v = row[ry * IN_W4];
            P += (v.x + v.y) + (v.z + v.w);
            if (do_extra) {
                float4 e = row[ry * IN_W4 + 32];   // next segment's first float4
                E += (e.x + e.y) + (e.z + e.w);
            }
        }

        float Pn  = __shfl_down_sync(0xffffffffu, P, 1);
        float Ebc = __shfl_sync(0xffffffffu, E, 0);
        float G = P + ((lane == 31) ? Ebc : Pn);

        if (g > r0 && tid < OUT_W) {
            yp[(size_t)(g - 1) * OUT_W] = prevG + G;
        }
        prevG = G;
    }
}

extern "C" void kernel_launch(void* const* d_in, const int* in_sizes, int n_in,
                              void* d_out, int out_size) {
    const float* x = (const float*)d_in[0];
    float* y = (float*)d_out;
    dim3 grid(8 * 32, (OUT_H + BAND - 1) / BAND);   // 256 planes x 8 bands
    boxsum8s4_kernel<<<grid, THREADS>>>(x, y);
}

// round 4
// speedup vs baseline: 1.2415x; 1.0294x over previous
#include <cuda_runtime.h>
#include <cuda_bf16.h>
#include <cstdint>

// Box-sum 8x8 stride 4 over (8,32,512,512) fp32 NCHW -> (8,32,127,127).
// A 4-row group of one plane is a contiguous 8KB gmem block. Stage groups
// into a 3-deep smem ring via cp.async.bulk + mbarrier (complete_tx), so
// DRAM latency is hidden by the copy engine, not warp parallelism.
// Consumer thread t sums its own float4 column (cols 4t..4t+3) over the 4
// rows -> P; G[t] = P[t] + P[t+1] via shfl_down; warp seam (lane 31) reads
// the neighbor float4 straight from smem. out[g-1] = G_{g-1} + G_g.

#define OUT_H 127
#define OUT_W 127
#define BAND 32
#define THREADS 128
#define STAGES 3
#define GROUP_BYTES 8192          // 4 rows * 512 cols * 4B
#define ROW_F4 128                // float4 per input row

__device__ __forceinline__ uint32_t smem_u32(const void* p) {
    uint32_t a;
    asm("{ .reg .u64 t; cvta.to.shared.u64 t, %1; cvt.u32.u64 %0, t; }"
        : "=r"(a) : "l"(p));
    return a;
}
__device__ __forceinline__ void mbar_init(uint32_t mbar, uint32_t count) {
    asm volatile("mbarrier.init.shared.b64 [%0], %1;" :: "r"(mbar), "r"(count) : "memory");
}
__device__ __forceinline__ void mbar_arrive(uint32_t mbar) {
    asm volatile("mbarrier.arrive.shared.b64 _, [%0];" :: "r"(mbar) : "memory");
}
__device__ __forceinline__ void mbar_expect_tx(uint32_t mbar, uint32_t bytes) {
    asm volatile("mbarrier.arrive.expect_tx.shared.b64 _, [%0], %1;"
                 :: "r"(mbar), "r"(bytes) : "memory");
}
__device__ __forceinline__ void mbar_wait(uint32_t mbar, uint32_t parity) {
    uint32_t done;
    asm volatile(
        "{\n\t.reg .pred p;\n\t"
        "mbarrier.try_wait.parity.acquire.cta.shared::cta.b64 p, [%1], %2;\n\t"
        "selp.b32 %0, 1, 0, p;\n\t}"
        : "=r"(done) : "r"(mbar), "r"(parity) : "memory");
    if (!done) {
        asm volatile(
            "{\n\t.reg .pred P1;\n\t"
            "W_%=:\n\t"
            "mbarrier.try_wait.parity.acquire.cta.shared::cta.b64 P1, [%0], %1, 0x989680;\n\t"
            "@P1 bra.uni D_%=;\n\t"
            "bra.uni W_%=;\n\t"
            "D_%=:\n\t}"
            :: "r"(mbar), "r"(parity) : "memory");
    }
}
__device__ __forceinline__ void bulk_copy_g2s(uint32_t dst, const void* src,
                                              uint32_t bytes, uint32_t mbar) {
    asm volatile(
        "cp.async.bulk.shared::cta.global.mbarrier::complete_tx::bytes "
        "[%0], [%1], %2, [%3];"
        :: "r"(dst), "l"(src), "r"(bytes), "r"(mbar) : "memory");
}

__global__ __launch_bounds__(THREADS)
void boxsum8s4_kernel(const float* __restrict__ x, float* __restrict__ y) {
    __shared__ __align__(16) float4 stg[STAGES * 512];   // 3 x 8KB stages
    __shared__ __align__(8) uint64_t mb[2 * STAGES];      // full[0..2], empty[0..2]

    const int plane = blockIdx.x;            // 0..255
    const int band  = blockIdx.y;            // 0..3
    const int r0 = band * BAND;
    const int r1 = min(r0 + BAND, OUT_H);
    const int nG = r1 - r0 + 1;              // groups to stage (32 or 33)

    const int tid  = threadIdx.x;            // 0..127 = float4 column index
    const int lane = tid & 31;

    const uint32_t mb_base = smem_u32(mb);
    const uint32_t full0  = mb_base;
    const uint32_t empty0 = mb_base + STAGES * 8;
    const uint32_t stg0   = smem_u32(stg);

    if (tid == 0) {
        #pragma unroll
        for (int s = 0; s < STAGES; ++s) {
            mbar_init(full0  + s * 8, 1);        // tx-based completion
            mbar_init(empty0 + s * 8, THREADS);  // all threads release
        }
    }
    __syncthreads();

    const char* gsrc = (const char*)(x + (size_t)plane * 512 * 512) +
                       (size_t)r0 * GROUP_BYTES;
    float* yp = y + (size_t)plane * OUT_H * OUT_W + tid;

    // Prologue: fill the ring.
    if (tid == 0) {
        #pragma unroll
        for (int k = 0; k < STAGES; ++k) {
            if (k < nG) {
                mbar_expect_tx(full0 + k * 8, GROUP_BYTES);
                bulk_copy_g2s(stg0 + k * GROUP_BYTES, gsrc + (size_t)k * GROUP_BYTES,
                              GROUP_BYTES, full0 + k * 8);
            }
        }
    }

    const bool seam = (lane == 31) && (tid < 127);
    float prevG = 0.0f;

    for (int k = 0; k < nG; ++k) {
        const int s = k % STAGES;
        const uint32_t ph = (uint32_t)(k / STAGES) & 1u;

        mbar_wait(full0 + s * 8, ph);

        const float4* st = stg + s * 512;
        float P = 0.0f, E = 0.0f;
        #pragma unroll
        for (int ry = 0; ry < 4; ++ry) {
            float4 v = st[ry * ROW_F4 + tid];
            P += (v.x + v.y) + (v.z + v.w);
        }
        if (seam) {
            #pragma unroll
            for (int ry = 0; ry < 4; ++ry) {
                float4 e = st[ry * ROW_F4 + tid + 1];
                E += (e.x + e.y) + (e.z + e.w);
            }
        }
        float Pn = __shfl_down_sync(0xffffffffu, P, 1);
        float G  = P + (seam ? E : Pn);

        if (k > 0 && tid < OUT_W) {
            yp[(size_t)(r0 + k - 1) * OUT_W] = prevG + G;
        }
        prevG = G;

        mbar_arrive(empty0 + s * 8);

        // Producer: refill this stage with group k+STAGES once freed.
        if (tid == 0 && k + STAGES < nG) {
            mbar_wait(empty0 + s * 8, ph);
            mbar_expect_tx(full0 + s * 8, GROUP_BYTES);
            bulk_copy_g2s(stg0 + s * GROUP_BYTES,
                          gsrc + (size_t)(k + STAGES) * GROUP_BYTES,
                          GROUP_BYTES, full0 + s * 8);
        }
    }
}

extern "C" void kernel_launch(void* const* d_in, const int* in_sizes, int n_in,
                              void* d_out, int out_size) {
    const float* x = (const float*)d_in[0];
    float* y = (float*)d_out;
    dim3 grid(8 * 32, (OUT_H + BAND - 1) / BAND);   // 256 planes x 4 bands = 1024
    boxsum8s4_kernel<<<grid, THREADS>>>(x, y);
}

// round 5
// speedup vs baseline: 1.2473x; 1.0047x over previous
#include <cuda_runtime.h>
#include <cuda_bf16.h>
#include <cstdint>

// Box-sum 8x8 stride 4 over (8,32,512,512) fp32 NCHW -> (8,32,127,127).
// Pipeline v2: stage = TWO 4-row groups (16 KB contiguous gmem), 3-deep smem
// ring via cp.async.bulk + mbarrier. Refill for the stage freed last
// iteration is issued BEFORE computing the current stage, keeping >=2 stages
// (32 KB) in flight per CTA. Consumer thread t sums its own float4 column
// over each 4-row group -> P; G = P[t] + P[t+1] (shfl, smem seam at lane 31).

#define OUT_H 127
#define OUT_W 127
#define BAND 32
#define THREADS 128
#define STAGES 3
#define PAIR_BYTES 16384          // 2 groups * 8 KB
#define GROUP_BYTES 8192
#define ROW_F4 128

__device__ __forceinline__ uint32_t smem_u32(const void* p) {
    uint32_t a;
    asm("{ .reg .u64 t; cvta.to.shared.u64 t, %1; cvt.u32.u64 %0, t; }"
        : "=r"(a) : "l"(p));
    return a;
}
__device__ __forceinline__ void mbar_init(uint32_t mbar, uint32_t count) {
    asm volatile("mbarrier.init.shared.b64 [%0], %1;" :: "r"(mbar), "r"(count) : "memory");
}
__device__ __forceinline__ void mbar_arrive(uint32_t mbar) {
    asm volatile("mbarrier.arrive.shared.b64 _, [%0];" :: "r"(mbar) : "memory");
}
__device__ __forceinline__ void mbar_expect_tx(uint32_t mbar, uint32_t bytes) {
    asm volatile("mbarrier.arrive.expect_tx.shared.b64 _, [%0], %1;"
                 :: "r"(mbar), "r"(bytes) : "memory");
}
__device__ __forceinline__ void mbar_wait(uint32_t mbar, uint32_t parity) {
    uint32_t done;
    asm volatile(
        "{\n\t.reg .pred p;\n\t"
        "mbarrier.try_wait.parity.acquire.cta.shared::cta.b64 p, [%1], %2;\n\t"
        "selp.b32 %0, 1, 0, p;\n\t}"
        : "=r"(done) : "r"(mbar), "r"(parity) : "memory");
    if (!done) {
        asm volatile(
            "{\n\t.reg .pred P1;\n\t"
            "W_%=:\n\t"
            "mbarrier.try_wait.parity.acquire.cta.shared::cta.b64 P1, [%0], %1, 0x989680;\n\t"
            "@P1 bra.uni D_%=;\n\t"
            "bra.uni W_%=;\n\t"
            "D_%=:\n\t}"
            :: "r"(mbar), "r"(parity) : "memory");
    }
}
__device__ __forceinline__ void bulk_copy_g2s(uint32_t dst, const void* src,
                                              uint32_t bytes, uint32_t mbar) {
    asm volatile(
        "cp.async.bulk.shared::cta.global.mbarrier::complete_tx::bytes "
        "[%0], [%1], %2, [%3];"
        :: "r"(dst), "l"(src), "r"(bytes), "r"(mbar) : "memory");
}

__global__ __launch_bounds__(THREADS)
void boxsum8s4_kernel(const float* __restrict__ x, float* __restrict__ y) {
    extern __shared__ __align__(16) float4 stg[];        // STAGES * 1024 float4
    __shared__ __align__(8) uint64_t mb[2 * STAGES];     // full[0..2], empty[0..2]

    const int plane = blockIdx.x;            // 0..255
    const int band  = blockIdx.y;            // 0..3
    const int r0 = band * BAND;
    const int r1 = min(r0 + BAND, OUT_H);
    const int nG = r1 - r0 + 1;              // 33 (bands 0-2) or 32 (band 3)
    const int nP = (nG + 1) >> 1;            // pairs (17 or 16)

    const int tid  = threadIdx.x;            // 0..127 = float4 column index
    const int lane = tid & 31;

    const uint32_t mbb    = smem_u32(mb);
    const uint32_t full0  = mbb;
    const uint32_t empty0 = mbb + STAGES * 8;
    const uint32_t stg0   = smem_u32(stg);

    if (tid == 0) {
        #pragma unroll
        for (int s = 0; s < STAGES; ++s) {
            mbar_init(full0  + s * 8, 1);
            mbar_init(empty0 + s * 8, THREADS);
        }
    }
    __syncthreads();

    const char* gsrc = (const char*)(x + (size_t)plane * 512 * 512) +
                       (size_t)r0 * GROUP_BYTES;
    float* yp = y + (size_t)plane * OUT_H * OUT_W + tid;

    // Prologue: fill all 3 stages with pairs 0..2.
    if (tid == 0) {
        #pragma unroll
        for (int p = 0; p < STAGES; ++p) {
            const int rem = nG - 2 * p;
            const uint32_t bytes = (rem >= 2) ? PAIR_BYTES : GROUP_BYTES;
            mbar_expect_tx(full0 + p * 8, bytes);
            bulk_copy_g2s(stg0 + p * PAIR_BYTES, gsrc + (size_t)p * PAIR_BYTES,
                          bytes, full0 + p * 8);
        }
    }

    const bool seam = (lane == 31) && (tid < 127);
    float prevG = 0.0f;

    for (int j = 0; j < nP; ++j) {
        const int s = j % STAGES;

        // Refill the stage freed at iteration j-1 with pair j+2 (issued
        // BEFORE compute so the copy overlaps this iteration's work).
        if (tid == 0 && j >= 1 && j + 2 < nP) {
            const int s2 = (j - 1) % STAGES;
            mbar_wait(empty0 + s2 * 8, (uint32_t)((j - 1) / STAGES) & 1u);
            const int p = j + 2;
            const int rem = nG - 2 * p;
            const uint32_t bytes = (rem >= 2) ? PAIR_BYTES : GROUP_BYTES;
            mbar_expect_tx(full0 + s2 * 8, bytes);
            bulk_copy_g2s(stg0 + s2 * PAIR_BYTES, gsrc + (size_t)p * PAIR_BYTES,
                          bytes, full0 + s2 * 8);
        }

        mbar_wait(full0 + s * 8, (uint32_t)(j / STAGES) & 1u);

        const float4* st = stg + (size_t)s * 1024;
        const int k0 = 2 * j;

        // Group k0: rows 0..3 of stage.
        float P0 = 0.0f, E0 = 0.0f;
        #pragma unroll
        for (int ry = 0; ry < 4; ++ry) {
            float4 v = st[ry * ROW_F4 + tid];
            P0 += (v.x + v.y) + (v.z + v.w);
        }
        if (seam) {
            #pragma unroll
            for (int ry = 0; ry < 4; ++ry) {
                float4 e = st[ry * ROW_F4 + tid + 1];
                E0 += (e.x + e.y) + (e.z + e.w);
            }
        }
        float Pn0 = __shfl_down_sync(0xffffffffu, P0, 1);
        float G0  = P0 + (seam ? E0 : Pn0);

        if (k0 > 0 && tid < OUT_W)
            yp[(size_t)(r0 + k0 - 1) * OUT_W] = prevG + G0;
        prevG = G0;

        // Group k0+1: rows 4..7 of stage (if present).
        if (k0 + 1 < nG) {
            float P1 = 0.0f, E1 = 0.0f;
            #pragma unroll
            for (int ry = 4; ry < 8; ++ry) {
                float4 v = st[ry * ROW_F4 + tid];
                P1 += (v.x + v.y) + (v.z + v.w);
            }
            if (seam) {
                #pragma unroll
                for (int ry = 4; ry < 8; ++ry) {
                    float4 e = st[ry * ROW_F4 + tid + 1];
                    E1 += (e.x + e.y) + (e.z + e.w);
                }
            }
            float Pn1 = __shfl_down_sync(0xffffffffu, P1, 1);
            float G1  = P1 + (seam ? E1 : Pn1);

            if (tid < OUT_W)
                yp[(size_t)(r0 + k0) * OUT_W] = G0 + G1;
            prevG = G1;
        }

        mbar_arrive(empty0 + s * 8);
    }
}

extern "C" void kernel_launch(void* const* d_in, const int* in_sizes, int n_in,
                              void* d_out, int out_size) {
    const float* x = (const float*)d_in[0];
    float* y = (float*)d_out;
    const int smem = STAGES * PAIR_BYTES;                 // 48 KB dynamic
    cudaFuncSetAttribute(boxsum8s4_kernel,
                         cudaFuncAttributeMaxDynamicSharedMemorySize, smem);
    dim3 grid(8 * 32, (OUT_H + BAND - 1) / BAND);         // 256 x 4 = 1024
    boxsum8s4_kernel<<<grid, THREADS, smem>>>(x, y);
}